// round 1
// baseline (speedup 1.0000x reference)
#include <cuda_runtime.h>
#include <cuda_bf16.h>

// SmoothnessLoss: loss = mean_i( (sHat_i - sY_i)^2 ), i in [0, N-k-1)
// s_i = sum_{j<k} | x[i+j] - mean_{j<k}(x[i+j]) |
// k is fixed at 64 for this problem instance.

#define K_WIN 64
#define BLOCK 256
#define TILE (BLOCK + K_WIN)   // 320 elements per array per block

// Scratch for per-block partial sums (max 2^17 blocks -> 32M windows, plenty)
__device__ float g_partials[1 << 17];

__global__ void __launch_bounds__(BLOCK)
smoothness_fused_kernel(const float* __restrict__ yh,
                        const float* __restrict__ yy,
                        int W, int N)
{
    __shared__ float sh[TILE];
    __shared__ float sy[TILE];
    __shared__ float red[BLOCK / 32];

    const int base = blockIdx.x * BLOCK;

    // Cooperative tile load (256 windows + 64-element halo)
    #pragma unroll
    for (int t = threadIdx.x; t < TILE; t += BLOCK) {
        int g = base + t;
        float vh = 0.f, vy = 0.f;
        if (g < N) { vh = yh[g]; vy = yy[g]; }
        sh[t] = vh;
        sy[t] = vy;
    }
    __syncthreads();

    float d2 = 0.f;
    const int i = base + threadIdx.x;
    if (i < W) {
        const int t = threadIdx.x;

        // Pass 1: window sums -> means
        float s1 = 0.f, s2 = 0.f;
        #pragma unroll
        for (int j = 0; j < K_WIN; j++) {
            s1 += sh[t + j];
            s2 += sy[t + j];
        }
        const float m1 = s1 * (1.0f / K_WIN);
        const float m2 = s2 * (1.0f / K_WIN);

        // Pass 2: sum |x - m|
        float a1 = 0.f, a2 = 0.f;
        #pragma unroll
        for (int j = 0; j < K_WIN; j++) {
            a1 += fabsf(sh[t + j] - m1);
            a2 += fabsf(sy[t + j] - m2);
        }

        const float d = a1 - a2;
        d2 = d * d;
    }

    // Block reduction: warp shuffle then smem
    #pragma unroll
    for (int off = 16; off > 0; off >>= 1)
        d2 += __shfl_down_sync(0xffffffffu, d2, off);

    const int lane = threadIdx.x & 31;
    const int wid  = threadIdx.x >> 5;
    if (lane == 0) red[wid] = d2;
    __syncthreads();

    if (wid == 0) {
        float v = (lane < BLOCK / 32) ? red[lane] : 0.f;
        #pragma unroll
        for (int off = 4; off > 0; off >>= 1)
            v += __shfl_down_sync(0xffffffffu, v, off);
        if (lane == 0) g_partials[blockIdx.x] = v;
    }
}

__global__ void __launch_bounds__(256)
smoothness_reduce_kernel(float* __restrict__ out, int nblocks, double invW)
{
    __shared__ double red[8];
    double s = 0.0;
    for (int i = threadIdx.x; i < nblocks; i += 256)
        s += (double)g_partials[i];

    #pragma unroll
    for (int off = 16; off > 0; off >>= 1)
        s += __shfl_down_sync(0xffffffffu, s, off);

    const int lane = threadIdx.x & 31;
    const int wid  = threadIdx.x >> 5;
    if (lane == 0) red[wid] = s;
    __syncthreads();

    if (wid == 0) {
        double v = (lane < 8) ? red[lane] : 0.0;
        #pragma unroll
        for (int off = 4; off > 0; off >>= 1)
            v += __shfl_down_sync(0xffffffffu, v, off);
        if (lane == 0) out[0] = (float)(v * invW);
    }
}

extern "C" void kernel_launch(void* const* d_in, const int* in_sizes, int n_in,
                              void* d_out, int out_size)
{
    const float* yh = (const float*)d_in[0];
    const float* yy = (const float*)d_in[1];
    const int N = in_sizes[0];
    const int W = N - K_WIN - 1;          // matches range(N - k - 1)
    const int nblocks = (W + BLOCK - 1) / BLOCK;

    smoothness_fused_kernel<<<nblocks, BLOCK>>>(yh, yy, W, N);
    smoothness_reduce_kernel<<<1, 256>>>((float*)d_out, nblocks, 1.0 / (double)W);
}

// round 2
// speedup vs baseline: 2.1415x; 2.1415x over previous
#include <cuda_runtime.h>
#include <cuda_bf16.h>

// SmoothnessLoss: loss = mean_i( (sHat_i - sY_i)^2 ), i in [0, W), W = N-k-1
// s_i = sum_{j<k} | x[i+j] - mean_j |, k = 64.

#define K_WIN 64
#define BLOCK 256
#define WPT 4                                // windows per thread
#define WIN_PER_BLOCK (BLOCK * WPT)          // 1024
#define TILE_ELEMS (WIN_PER_BLOCK + K_WIN)   // 1088 floats per array
#define TILE_F4 (TILE_ELEMS / 4)             // 272
#define CHUNKS 17                            // float4 per thread segment (68 floats)

typedef unsigned long long u64;

__device__ float g_partials[4096];

__device__ __forceinline__ u64 addx2(u64 a, u64 b) {
    u64 r; asm("add.rn.f32x2 %0, %1, %2;" : "=l"(r) : "l"(a), "l"(b)); return r;
}
__device__ __forceinline__ u64 pk(float lo, float hi) {
    u64 r; asm("mov.b64 %0, {%1, %2};" : "=l"(r) : "f"(lo), "f"(hi)); return r;
}
__device__ __forceinline__ void upk(u64 p, float& lo, float& hi) {
    asm("mov.b64 {%0, %1}, %2;" : "=f"(lo), "=f"(hi) : "l"(p));
}
__device__ __forceinline__ u64 absx2(u64 a) { return a & 0x7FFFFFFF7FFFFFFFULL; }

// Process one array's 68-float segment for this thread: 4 window sums -> 4 abs-dev sums.
__device__ __forceinline__ void process_seg(const float4* __restrict__ t4, int tid,
                                            float a[WPT])
{
    u64 v[2 * CHUNKS];                 // 34 packed pairs = 68 floats
    #pragma unroll
    for (int q = 0; q < CHUNKS; q++) {
        float4 c = t4[tid + q];
        v[2 * q]     = pk(c.x, c.y);
        v[2 * q + 1] = pk(c.z, c.w);
    }

    // Pass 1: s0 = sum of elements [0,64) via packed tree, then sliding shifts.
    u64 acc = v[0];
    #pragma unroll
    for (int p = 1; p < 32; p++) acc = addx2(acc, v[p]);
    float lo, hi; upk(acc, lo, hi);
    float s[WPT];
    s[0] = lo + hi;
    float e0, e1, e2, e3, f0, f1, f2, f3;
    upk(v[0],  e0, e1); upk(v[1],  e2, e3);   // elements 0,1,2,3
    upk(v[32], f0, f1); upk(v[33], f2, f3);   // elements 64,65,66,67
    s[1] = s[0] - e0 + f0;
    s[2] = s[1] - e1 + f1;
    s[3] = s[2] - e2 + f2;
    (void)e3; (void)f3;

    const float invk = 1.0f / (float)K_WIN;

    // Pass 2: per window w, sum |x - m| over elements [w, w+64).
    #pragma unroll
    for (int w = 0; w < WPT; w++) {
        const float m = s[w] * invk;
        const u64 nm2 = pk(-m, -m);
        u64 aa = 0ULL;
        float extra = 0.0f;
        if ((w & 1) == 0) {
            const int p0 = w >> 1;             // 32 aligned pairs
            #pragma unroll
            for (int p = 0; p < 32; p++)
                aa = addx2(aa, absx2(addx2(v[p0 + p], nm2)));
        } else {
            const int p0 = (w + 1) >> 1;       // 31 aligned interior pairs + 2 scalar ends
            #pragma unroll
            for (int p = 0; p < 31; p++)
                aa = addx2(aa, absx2(addx2(v[p0 + p], nm2)));
            float t0, t1, x0, x1;
            upk(v[w >> 1], t0, t1);        x0 = t1;   // element w (odd -> hi half)
            upk(v[(w + 63) >> 1], t0, t1); x1 = t0;   // element w+63 (even -> lo half)
            extra = fabsf(x0 - m) + fabsf(x1 - m);
        }
        float al, ah; upk(aa, al, ah);
        a[w] = al + ah + extra;
    }
}

__global__ void __launch_bounds__(BLOCK, 2)
smoothness_main_kernel(const float* __restrict__ yh,
                       const float* __restrict__ yy,
                       int W, int N)
{
    __shared__ float4 sh4[TILE_F4];
    __shared__ float4 sy4[TILE_F4];
    __shared__ float red[BLOCK / 32];

    const int tid  = threadIdx.x;
    const int base = blockIdx.x * WIN_PER_BLOCK;   // element base of this tile
    const int b4   = base >> 2;                    // float4 base

    // Cooperative tile load (vectorized, guarded at the array end).
    #pragma unroll
    for (int q = tid; q < TILE_F4; q += BLOCK) {
        const int g = base + 4 * q;
        float4 vh, vy;
        if (g + 3 < N) {
            vh = reinterpret_cast<const float4*>(yh)[b4 + q];
            vy = reinterpret_cast<const float4*>(yy)[b4 + q];
        } else {
            float h[4], y[4];
            #pragma unroll
            for (int j = 0; j < 4; j++) {
                const bool ok = (g + j) < N;
                h[j] = ok ? yh[g + j] : 0.0f;
                y[j] = ok ? yy[g + j] : 0.0f;
            }
            vh = make_float4(h[0], h[1], h[2], h[3]);
            vy = make_float4(y[0], y[1], y[2], y[3]);
        }
        sh4[q] = vh;
        sy4[q] = vy;
    }
    __syncthreads();

    float a1[WPT], a2[WPT];
    process_seg(sh4, tid, a1);
    process_seg(sy4, tid, a2);

    float d2 = 0.0f;
    const int i0 = base + WPT * tid;
    #pragma unroll
    for (int w = 0; w < WPT; w++) {
        if (i0 + w < W) {
            const float d = a1[w] - a2[w];
            d2 += d * d;
        }
    }

    // Block reduction
    #pragma unroll
    for (int off = 16; off > 0; off >>= 1)
        d2 += __shfl_down_sync(0xffffffffu, d2, off);

    const int lane = tid & 31, wid = tid >> 5;
    if (lane == 0) red[wid] = d2;
    __syncthreads();
    if (wid == 0) {
        float v = (lane < BLOCK / 32) ? red[lane] : 0.0f;
        #pragma unroll
        for (int off = 4; off > 0; off >>= 1)
            v += __shfl_down_sync(0xffffffffu, v, off);
        if (lane == 0) g_partials[blockIdx.x] = v;
    }
}

__global__ void __launch_bounds__(1024)
smoothness_reduce_kernel(float* __restrict__ out, int nblocks, double invW)
{
    __shared__ double red[32];
    double sacc = 0.0;
    for (int i = threadIdx.x; i < nblocks; i += 1024)
        sacc += (double)g_partials[i];

    #pragma unroll
    for (int off = 16; off > 0; off >>= 1)
        sacc += __shfl_down_sync(0xffffffffu, sacc, off);

    const int lane = threadIdx.x & 31, wid = threadIdx.x >> 5;
    if (lane == 0) red[wid] = sacc;
    __syncthreads();
    if (wid == 0) {
        double v = (lane < 32) ? red[lane] : 0.0;
        #pragma unroll
        for (int off = 16; off > 0; off >>= 1)
            v += __shfl_down_sync(0xffffffffu, v, off);
        if (lane == 0) out[0] = (float)(v * invW);
    }
}

extern "C" void kernel_launch(void* const* d_in, const int* in_sizes, int n_in,
                              void* d_out, int out_size)
{
    const float* yh = (const float*)d_in[0];
    const float* yy = (const float*)d_in[1];
    const int N = in_sizes[0];
    const int W = N - K_WIN - 1;
    const int nblocks = (W + WIN_PER_BLOCK - 1) / WIN_PER_BLOCK;

    smoothness_main_kernel<<<nblocks, BLOCK>>>(yh, yy, W, N);
    smoothness_reduce_kernel<<<1, 1024>>>((float*)d_out, nblocks, 1.0 / (double)W);
}

// round 3
// speedup vs baseline: 2.3765x; 1.1098x over previous
#include <cuda_runtime.h>
#include <cuda_bf16.h>

// SmoothnessLoss: loss = mean_i( (sHat_i - sY_i)^2 ), i in [0, W), W = N-k-1
// s_i = sum_{j<k} | x[i+j] - mean_j |, k = 64.
// Single persistent kernel: 296 balanced blocks, fused deterministic reduction.

#define K_WIN 64
#define BLOCK 256
#define WPT 4
#define SUBTILE (BLOCK * WPT)                // 1024 windows per subtile
#define TILE_ELEMS (SUBTILE + K_WIN)         // 1088 floats
#define TILE_F4 (TILE_ELEMS / 4)             // 272
#define CHUNKS 17                            // float4 per thread segment (68 floats)
#define GRID 296                             // 2 blocks/SM x 148 SMs

typedef unsigned long long u64;

__device__ float g_partials[GRID];
__device__ unsigned int g_count = 0;

__device__ __forceinline__ u64 addx2(u64 a, u64 b) {
    u64 r; asm("add.rn.f32x2 %0, %1, %2;" : "=l"(r) : "l"(a), "l"(b)); return r;
}
__device__ __forceinline__ u64 pk(float lo, float hi) {
    u64 r; asm("mov.b64 %0, {%1, %2};" : "=l"(r) : "f"(lo), "f"(hi)); return r;
}
__device__ __forceinline__ void upk(u64 p, float& lo, float& hi) {
    asm("mov.b64 {%0, %1}, %2;" : "=f"(lo), "=f"(hi) : "l"(p));
}
__device__ __forceinline__ u64 absx2(u64 a) { return a & 0x7FFFFFFF7FFFFFFFULL; }

// One array's 68-float segment: 4 window sums -> 4 abs-deviation sums.
__device__ __forceinline__ void process_seg(const ulonglong2* __restrict__ t2, int tid,
                                            float a[WPT])
{
    u64 v[2 * CHUNKS];                 // 34 packed pairs = 68 floats
    #pragma unroll
    for (int q = 0; q < CHUNKS; q++) {
        ulonglong2 c = t2[tid + q];
        v[2 * q]     = c.x;
        v[2 * q + 1] = c.y;
    }

    // Pass 1: window sums via packed tree + sliding updates.
    u64 acc = v[0];
    #pragma unroll
    for (int p = 1; p < 32; p++) acc = addx2(acc, v[p]);
    float lo, hi; upk(acc, lo, hi);
    float s[WPT];
    s[0] = lo + hi;
    float e0, e1, e2, e3, f0, f1, f2, f3;
    upk(v[0],  e0, e1); upk(v[1],  e2, e3);   // elements 0..3
    upk(v[32], f0, f1); upk(v[33], f2, f3);   // elements 64..67
    s[1] = s[0] - e0 + f0;
    s[2] = s[1] - e1 + f1;
    s[3] = s[2] - e2 + f2;
    (void)e3; (void)f3;

    const float invk = 1.0f / (float)K_WIN;

    // Pass 2: per window w, sum |x - m|.
    #pragma unroll
    for (int w = 0; w < WPT; w++) {
        const float m = s[w] * invk;
        const u64 nm2 = pk(-m, -m);
        u64 aa = 0ULL;
        float extra = 0.0f;
        if ((w & 1) == 0) {
            const int p0 = w >> 1;             // 32 aligned pairs
            #pragma unroll
            for (int p = 0; p < 32; p++)
                aa = addx2(aa, absx2(addx2(v[p0 + p], nm2)));
        } else {
            const int p0 = (w + 1) >> 1;       // 31 aligned interior pairs + 2 scalar ends
            #pragma unroll
            for (int p = 0; p < 31; p++)
                aa = addx2(aa, absx2(addx2(v[p0 + p], nm2)));
            float t0, t1, x0, x1;
            upk(v[w >> 1], t0, t1);        x0 = t1;   // element w (odd -> hi half)
            upk(v[(w + 63) >> 1], t0, t1); x1 = t0;   // element w+63 (even -> lo half)
            extra = fabsf(x0 - m) + fabsf(x1 - m);
        }
        float al, ah; upk(aa, al, ah);
        a[w] = al + ah + extra;
    }
}

__global__ void __launch_bounds__(BLOCK, 2)
smoothness_persist_kernel(const float* __restrict__ yh,
                          const float* __restrict__ yy,
                          int W, int N, int WB,
                          float* __restrict__ out, double invW)
{
    __shared__ float4 sh4[TILE_F4];
    __shared__ float4 sy4[TILE_F4];
    __shared__ float  redf[BLOCK / 32];
    __shared__ double redd[BLOCK / 32];
    __shared__ int    amLast;

    const int tid    = threadIdx.x;
    const int wstart = blockIdx.x * WB;            // multiple of 4
    const int wend   = min(wstart + WB, W);

    float d2 = 0.0f;

    for (int base = wstart; base < wend; base += SUBTILE) {
        const int b4 = base >> 2;
        // Cooperative tile load (vectorized, guarded at array end).
        #pragma unroll
        for (int q = tid; q < TILE_F4; q += BLOCK) {
            const int g = base + 4 * q;
            float4 vh, vy;
            if (g + 3 < N) {
                vh = reinterpret_cast<const float4*>(yh)[b4 + q];
                vy = reinterpret_cast<const float4*>(yy)[b4 + q];
            } else {
                float h[4], y[4];
                #pragma unroll
                for (int j = 0; j < 4; j++) {
                    const bool ok = (g + j) < N;
                    h[j] = ok ? yh[g + j] : 0.0f;
                    y[j] = ok ? yy[g + j] : 0.0f;
                }
                vh = make_float4(h[0], h[1], h[2], h[3]);
                vy = make_float4(y[0], y[1], y[2], y[3]);
            }
            sh4[q] = vh;
            sy4[q] = vy;
        }
        __syncthreads();

        const int i0 = base + WPT * tid;
        if (i0 < wend) {
            float a1[WPT], a2[WPT];
            process_seg(reinterpret_cast<const ulonglong2*>(sh4), tid, a1);
            process_seg(reinterpret_cast<const ulonglong2*>(sy4), tid, a2);
            #pragma unroll
            for (int w = 0; w < WPT; w++) {
                if (i0 + w < wend) {
                    const float d = a1[w] - a2[w];
                    d2 += d * d;
                }
            }
        }
        __syncthreads();   // before smem reuse next iteration
    }

    // Block reduction of d2.
    #pragma unroll
    for (int off = 16; off > 0; off >>= 1)
        d2 += __shfl_down_sync(0xffffffffu, d2, off);

    const int lane = tid & 31, wid = tid >> 5;
    if (lane == 0) redf[wid] = d2;
    __syncthreads();
    if (wid == 0) {
        float v = (lane < BLOCK / 32) ? redf[lane] : 0.0f;
        #pragma unroll
        for (int off = 4; off > 0; off >>= 1)
            v += __shfl_down_sync(0xffffffffu, v, off);
        if (lane == 0) {
            g_partials[blockIdx.x] = v;
            __threadfence();
            unsigned int c = atomicAdd(&g_count, 1u);
            amLast = (c == (unsigned int)(gridDim.x - 1));
        }
    }
    __syncthreads();

    if (amLast) {
        // Deterministic final reduction over GRID partials (fixed order/topology).
        double s = 0.0;
        for (int i = tid; i < GRID; i += BLOCK)
            s += (double)g_partials[i];
        #pragma unroll
        for (int off = 16; off > 0; off >>= 1)
            s += __shfl_down_sync(0xffffffffu, s, off);
        if (lane == 0) redd[wid] = s;
        __syncthreads();
        if (wid == 0) {
            double v = (lane < BLOCK / 32) ? redd[lane] : 0.0;
            #pragma unroll
            for (int off = 4; off > 0; off >>= 1)
                v += __shfl_down_sync(0xffffffffu, v, off);
            if (lane == 0) {
                out[0] = (float)(v * invW);
                g_count = 0;                 // reset for next graph replay
            }
        }
    }
}

extern "C" void kernel_launch(void* const* d_in, const int* in_sizes, int n_in,
                              void* d_out, int out_size)
{
    const float* yh = (const float*)d_in[0];
    const float* yy = (const float*)d_in[1];
    const int N = in_sizes[0];
    const int W = N - K_WIN - 1;
    // Windows per block: ceil(W/GRID), rounded up to a multiple of 4 (float4 alignment).
    int WB = (W + GRID - 1) / GRID;
    WB = (WB + 3) & ~3;

    smoothness_persist_kernel<<<GRID, BLOCK>>>(yh, yy, W, N, WB,
                                               (float*)d_out, 1.0 / (double)W);
}